// round 1
// baseline (speedup 1.0000x reference)
#include <cuda_runtime.h>
#include <math.h>

// ---------------- problem constants ----------------
#define T_TOK   2048
#define D_MODEL 1280
#define H_HEADS 16
#define HD      80
#define HALF    40
#define FF_DIM  3420
#define DEPTH   4
#define OUT_DIM 3584
#define PATCH_IN 1176
#define WIN     64
#define NWIN    (T_TOK / WIN)
#define EPS_RMS 1e-6f
#define ATT_SCALE 0.1118033988749895f   // 1/sqrt(80)

// ---------------- scratch (device globals; no allocation allowed) ----------------
__device__ float g_h  [T_TOK * D_MODEL];
__device__ float g_n  [T_TOK * D_MODEL];       // also viewed as [512, 5120]
__device__ float g_qkv[T_TOK * 3 * D_MODEL];
__device__ float g_att[T_TOK * D_MODEL];
__device__ float g_gate[T_TOK * FF_DIM];
__device__ float g_up  [T_TOK * FF_DIM];
__device__ float g_f1 [512 * 4 * D_MODEL];

// ---------------- tiled SGEMM with fused epilogues ----------------
// C[M,N] = epi(A[M,K] @ B[K,N]).  M must be a multiple of 128 (true for all calls).
// 128x128 tile, BK=16, 256 threads, 8x8 per-thread microtile.
enum {
    EPI_NONE = 0,
    EPI_BIAS,        // C = AB + b
    EPI_BIAS_SILU,   // C = silu(AB + b)
    EPI_BIAS_RES,    // C = R + AB + b        (R may alias C)
    EPI_BIAS_MUL,    // C = (AB + b) * R
    EPI_BIAS_GELU    // C = gelu_exact(AB + b)
};

template <int EPI>
__global__ __launch_bounds__(256)
void sgemm_kernel(const float* __restrict__ A, const float* __restrict__ B,
                  const float* __restrict__ bias, const float* __restrict__ R,
                  float* __restrict__ C, int M, int N, int K)
{
    __shared__ float As[16][128];
    __shared__ float Bs[16][128];

    const int tid  = threadIdx.x;
    const int tx   = tid & 15;        // 0..15  -> N direction
    const int ty   = tid >> 4;        // 0..15  -> M direction
    const int row0 = blockIdx.y * 128;
    const int col0 = blockIdx.x * 128;

    // A-tile load mapping: each thread loads 8 contiguous K elems of one row
    const int a_r = tid >> 1;            // 0..127
    const int a_c = (tid & 1) * 8;       // 0 or 8
    // B-tile load mapping: each thread loads 8 contiguous N elems of one K-row
    const int b_r = tid >> 4;            // 0..15
    const int b_c = (tid & 15) * 8;      // 0..120

    float acc[8][8];
#pragma unroll
    for (int i = 0; i < 8; i++)
#pragma unroll
        for (int j = 0; j < 8; j++) acc[i][j] = 0.f;

    const float* Arow = A + (size_t)(row0 + a_r) * K;

    for (int k0 = 0; k0 < K; k0 += 16) {
#pragma unroll
        for (int i = 0; i < 8; i++) {
            int gc = k0 + a_c + i;
            As[a_c + i][a_r] = (gc < K) ? Arow[gc] : 0.f;
        }
#pragma unroll
        for (int i = 0; i < 8; i++) {
            int gr = k0 + b_r;
            int gc = col0 + b_c + i;
            Bs[b_r][b_c + i] = (gr < K && gc < N) ? B[(size_t)gr * N + gc] : 0.f;
        }
        __syncthreads();

#pragma unroll
        for (int k = 0; k < 16; k++) {
            float a[8], b[8];
#pragma unroll
            for (int i = 0; i < 8; i++) a[i] = As[k][ty * 8 + i];
#pragma unroll
            for (int j = 0; j < 8; j++) b[j] = Bs[k][tx * 8 + j];
#pragma unroll
            for (int i = 0; i < 8; i++)
#pragma unroll
                for (int j = 0; j < 8; j++) acc[i][j] += a[i] * b[j];
        }
        __syncthreads();
    }

#pragma unroll
    for (int i = 0; i < 8; i++) {
        int r = row0 + ty * 8 + i;
#pragma unroll
        for (int j = 0; j < 8; j++) {
            int c = col0 + tx * 8 + j;
            if (c < N) {
                float v = acc[i][j];
                size_t idx = (size_t)r * N + c;
                if (EPI != EPI_NONE)      v += bias[c];
                if (EPI == EPI_BIAS_SILU) v = v / (1.f + expf(-v));
                if (EPI == EPI_BIAS_RES)  v += R[idx];
                if (EPI == EPI_BIAS_MUL)  v *= R[idx];
                if (EPI == EPI_BIAS_GELU) v = 0.5f * v * (1.f + erff(v * 0.7071067811865475f));
                C[idx] = v;
            }
        }
    }
}

// ---------------- rmsnorm: one block per row of D_MODEL ----------------
__global__ void rmsnorm_kernel(const float* __restrict__ x, const float* __restrict__ s,
                               float* __restrict__ y)
{
    const int row = blockIdx.x;
    const float* xr = x + (size_t)row * D_MODEL;
    float* yr = y + (size_t)row * D_MODEL;

    float sum = 0.f;
    for (int i = threadIdx.x; i < D_MODEL; i += 256) {
        float v = xr[i];
        sum += v * v;
    }
#pragma unroll
    for (int o = 16; o; o >>= 1) sum += __shfl_xor_sync(~0u, sum, o);

    __shared__ float red[8];
    const int warp = threadIdx.x >> 5, lane = threadIdx.x & 31;
    if (lane == 0) red[warp] = sum;
    __syncthreads();
    if (warp == 0) {
        float v = (lane < 8) ? red[lane] : 0.f;
#pragma unroll
        for (int o = 4; o; o >>= 1) v += __shfl_xor_sync(~0u, v, o);
        if (lane == 0) red[0] = v;
    }
    __syncthreads();

    const float rinv = rsqrtf(red[0] * (1.f / D_MODEL) + EPS_RMS);
    for (int i = threadIdx.x; i < D_MODEL; i += 256)
        yr[i] = xr[i] * s[i] * rinv;
}

// ---------------- RoPE in-place on q,k slices of qkv ----------------
__global__ void rope_kernel(float* __restrict__ qkv, const float* __restrict__ rot)
{
    const int per = T_TOK * H_HEADS * HALF;        // 1,310,720
    int idx = blockIdx.x * blockDim.x + threadIdx.x;
    if (idx >= 2 * per) return;
    const int which = (idx >= per) ? 1 : 0;        // 0=q, 1=k
    int rem = idx - which * per;
    const int t  = rem / (H_HEADS * HALF);
    const int r2 = rem % (H_HEADS * HALF);
    const int hh = r2 / HALF;
    const int d  = r2 % HALF;

    const float ang = rot[t * HALF + d];
    float s, c;
    sincosf(ang, &s, &c);

    float* p = qkv + (size_t)t * (3 * D_MODEL) + which * D_MODEL + hh * HD + d;
    const float re = p[0], im = p[HALF];
    p[0]    = re * c - im * s;
    p[HALF] = re * s + im * c;
}

// ---------------- windowed attention: one CTA per (window, head) ----------------
// smem: q[64][80], k[64][81] (padded, conflict-free), v[64][80], probs[8][64]
#define ATT_SMEM ((64 * 80 + 64 * 81 + 64 * 80 + 8 * 64) * 4)

__global__ void attn_kernel(const float* __restrict__ qkv, float* __restrict__ out)
{
    extern __shared__ float sm[];
    float* qs = sm;                  // [64][80]
    float* ks = qs + 64 * 80;        // [64][81]
    float* vs = ks + 64 * 81;        // [64][80]
    float* pr = vs + 64 * 80;        // [8][64]

    const int w = blockIdx.x, hh = blockIdx.y;
    const int tid = threadIdx.x, lane = tid & 31, warp = tid >> 5;
    const size_t base = (size_t)w * WIN * (3 * D_MODEL) + hh * HD;

    for (int idx = tid; idx < WIN * HD; idx += 256) {
        const int t = idx / HD, d = idx % HD;
        const size_t g = base + (size_t)t * (3 * D_MODEL) + d;
        qs[t * 80 + d] = qkv[g];
        ks[t * 81 + d] = qkv[g + D_MODEL];
        vs[t * 80 + d] = qkv[g + 2 * D_MODEL];
    }
    __syncthreads();

    for (int row = warp; row < WIN; row += 8) {
        const float* qr = qs + row * 80;
        const float* k0 = ks + lane * 81;
        const float* k1 = ks + (lane + 32) * 81;
        float s0 = 0.f, s1 = 0.f;
#pragma unroll
        for (int d = 0; d < HD; d++) {
            const float q = qr[d];
            s0 += q * k0[d];
            s1 += q * k1[d];
        }
        s0 *= ATT_SCALE; s1 *= ATT_SCALE;

        float mx = fmaxf(s0, s1);
#pragma unroll
        for (int o = 16; o; o >>= 1) mx = fmaxf(mx, __shfl_xor_sync(~0u, mx, o));
        const float e0 = expf(s0 - mx), e1 = expf(s1 - mx);
        float sum = e0 + e1;
#pragma unroll
        for (int o = 16; o; o >>= 1) sum += __shfl_xor_sync(~0u, sum, o);
        const float inv = 1.f / sum;

        pr[warp * 64 + lane]      = e0 * inv;
        pr[warp * 64 + lane + 32] = e1 * inv;
        __syncwarp();

        float o0 = 0.f, o1 = 0.f, o2 = 0.f;
#pragma unroll 4
        for (int j = 0; j < WIN; j++) {
            const float p = pr[warp * 64 + j];
            const float* vr = vs + j * 80;
            o0 += p * vr[lane];
            o1 += p * vr[lane + 32];
            if (lane < 16) o2 += p * vr[lane + 64];
        }
        const size_t ob = (size_t)(w * WIN + row) * D_MODEL + hh * HD;
        out[ob + lane]      = o0;
        out[ob + lane + 32] = o1;
        if (lane < 16) out[ob + lane + 64] = o2;
        __syncwarp();
    }
}

// ---------------- host orchestration ----------------
static inline dim3 gg(int M, int N) { return dim3((N + 127) / 128, (M + 127) / 128); }

extern "C" void kernel_launch(void* const* d_in, const int* in_sizes, int n_in,
                              void* d_out, int out_size)
{
    const float* x      = (const float*)d_in[0];
    const float* rot    = (const float*)d_in[1];
    /* d_in[2] = cu_window_seqlens (fixed arange(0,T+1,64); windows hardcoded) */
    const float* patchw = (const float*)d_in[3];
    const float* qkvw   = (const float*)d_in[4];
    const float* qkvb   = (const float*)d_in[5];
    const float* projw  = (const float*)d_in[6];
    const float* projb  = (const float*)d_in[7];
    const float* n1s    = (const float*)d_in[8];
    const float* n2s    = (const float*)d_in[9];
    const float* gw     = (const float*)d_in[10];
    const float* gb     = (const float*)d_in[11];
    const float* uw     = (const float*)d_in[12];
    const float* ub     = (const float*)d_in[13];
    const float* dw     = (const float*)d_in[14];
    const float* db     = (const float*)d_in[15];
    const float* lnq    = (const float*)d_in[16];
    const float* f1w    = (const float*)d_in[17];
    const float* f1b    = (const float*)d_in[18];
    const float* f2w    = (const float*)d_in[19];
    const float* f2b    = (const float*)d_in[20];
    float* out = (float*)d_out;

    float *h, *n, *qkv, *att, *gate, *up, *f1;
    cudaGetSymbolAddress((void**)&h,    g_h);
    cudaGetSymbolAddress((void**)&n,    g_n);
    cudaGetSymbolAddress((void**)&qkv,  g_qkv);
    cudaGetSymbolAddress((void**)&att,  g_att);
    cudaGetSymbolAddress((void**)&gate, g_gate);
    cudaGetSymbolAddress((void**)&up,   g_up);
    cudaGetSymbolAddress((void**)&f1,   g_f1);

    cudaFuncSetAttribute(attn_kernel, cudaFuncAttributeMaxDynamicSharedMemorySize, ATT_SMEM);

    // patch embed: h = x @ patch_w
    sgemm_kernel<EPI_NONE><<<gg(T_TOK, D_MODEL), 256>>>(
        x, patchw, nullptr, nullptr, h, T_TOK, D_MODEL, PATCH_IN);

    for (int l = 0; l < DEPTH; l++) {
        const size_t lD = (size_t)l * D_MODEL;
        // n = rmsnorm(h, norm1)
        rmsnorm_kernel<<<T_TOK, 256>>>(h, n1s + lD, n);
        // qkv = n @ qkv_w + qkv_b
        sgemm_kernel<EPI_BIAS><<<gg(T_TOK, 3 * D_MODEL), 256>>>(
            n, qkvw + lD * 3 * D_MODEL, qkvb + (size_t)l * 3 * D_MODEL,
            nullptr, qkv, T_TOK, 3 * D_MODEL, D_MODEL);
        // rope q,k in-place
        rope_kernel<<<(2 * T_TOK * H_HEADS * HALF + 255) / 256, 256>>>(qkv, rot);
        // windowed attention
        attn_kernel<<<dim3(NWIN, H_HEADS), 256, ATT_SMEM>>>(qkv, att);
        // h = h + att @ proj_w + proj_b
        sgemm_kernel<EPI_BIAS_RES><<<gg(T_TOK, D_MODEL), 256>>>(
            att, projw + lD * D_MODEL, projb + lD, h, h, T_TOK, D_MODEL, D_MODEL);
        // n = rmsnorm(h, norm2)
        rmsnorm_kernel<<<T_TOK, 256>>>(h, n2s + lD, n);
        // gate = silu(n @ gw + gb)
        sgemm_kernel<EPI_BIAS_SILU><<<gg(T_TOK, FF_DIM), 256>>>(
            n, gw + lD * FF_DIM, gb + (size_t)l * FF_DIM, nullptr, gate,
            T_TOK, FF_DIM, D_MODEL);
        // up = (n @ uw + ub) * gate
        sgemm_kernel<EPI_BIAS_MUL><<<gg(T_TOK, FF_DIM), 256>>>(
            n, uw + lD * FF_DIM, ub + (size_t)l * FF_DIM, gate, up,
            T_TOK, FF_DIM, D_MODEL);
        // h = h + up @ dw + db
        sgemm_kernel<EPI_BIAS_RES><<<gg(T_TOK, D_MODEL), 256>>>(
            up, dw + (size_t)l * FF_DIM * D_MODEL, db + lD, h, h,
            T_TOK, D_MODEL, FF_DIM);
    }

    // final: n = rmsnorm(h, lnq); view as [512, 5120]
    rmsnorm_kernel<<<T_TOK, 256>>>(h, lnq, n);
    // f1 = gelu(n @ fc1_w + fc1_b)
    sgemm_kernel<EPI_BIAS_GELU><<<gg(512, 4 * D_MODEL), 256>>>(
        n, f1w, f1b, nullptr, f1, 512, 4 * D_MODEL, 4 * D_MODEL);
    // out = f1 @ fc2_w + fc2_b
    sgemm_kernel<EPI_BIAS><<<gg(512, OUT_DIM), 256>>>(
        f1, f2w, f2b, nullptr, out, 512, OUT_DIM, 4 * D_MODEL);
}

// round 3
// speedup vs baseline: 2.9600x; 2.9600x over previous
#include <cuda_runtime.h>
#include <cuda_bf16.h>
#include <math.h>
#include <stdint.h>

// ---------------- problem constants ----------------
#define T_TOK   2048
#define D_MODEL 1280
#define H_HEADS 16
#define HD      80
#define HALF    40
#define FF_DIM  3420
#define FF_PAD  3456
#define DEPTH   4
#define OUT_DIM 3584
#define PATCH_IN 1176
#define PATCH_KP 1216
#define WIN     64
#define NWIN    (T_TOK / WIN)
#define EPS_RMS 1e-6f
#define ATT_SCALE 0.1118033988749895f

typedef __nv_bfloat16 bf16;

// ---------------- helpers ----------------
__device__ __forceinline__ uint32_t smem_u32(const void* p) {
    uint32_t a;
    asm("{ .reg .u64 t; cvta.to.shared.u64 t, %1; cvt.u32.u64 %0, t; }" : "=r"(a) : "l"(p));
    return a;
}
__device__ __forceinline__ void cp_async16(uint32_t s, const void* g) {
    asm volatile("cp.async.cg.shared.global [%0], [%1], 16;" :: "r"(s), "l"(g));
}
#define CP_COMMIT() asm volatile("cp.async.commit_group;" ::: "memory")
#define CP_WAIT(n)  asm volatile("cp.async.wait_group %0;" :: "n"(n) : "memory")

__device__ __forceinline__ void ldm_x4(uint32_t& r0, uint32_t& r1, uint32_t& r2,
                                       uint32_t& r3, uint32_t addr) {
    asm volatile("ldmatrix.sync.aligned.m8n8.x4.shared.b16 {%0,%1,%2,%3}, [%4];"
                 : "=r"(r0), "=r"(r1), "=r"(r2), "=r"(r3) : "r"(addr));
}
__device__ __forceinline__ void mma16816(float* d, const uint32_t* a,
                                         uint32_t b0, uint32_t b1) {
    asm volatile("mma.sync.aligned.m16n8k16.row.col.f32.bf16.bf16.f32 "
                 "{%0,%1,%2,%3}, {%4,%5,%6,%7}, {%8,%9}, {%0,%1,%2,%3};"
                 : "+f"(d[0]), "+f"(d[1]), "+f"(d[2]), "+f"(d[3])
                 : "r"(a[0]), "r"(a[1]), "r"(a[2]), "r"(a[3]), "r"(b0), "r"(b1));
}

// ---------------- scratch ----------------
__device__ float g_h   [T_TOK * D_MODEL];
__device__ float g_qkv [T_TOK * 3 * D_MODEL];
__device__ float g_gate[(size_t)T_TOK * FF_DIM];
__device__ bf16  g_xh [T_TOK * PATCH_KP],      g_xl [T_TOK * PATCH_KP];
__device__ bf16  g_nh [T_TOK * D_MODEL],       g_nl [T_TOK * D_MODEL];
__device__ bf16  g_ath[T_TOK * D_MODEL],       g_atl[T_TOK * D_MODEL];
__device__ bf16  g_uph[(size_t)T_TOK * FF_PAD], g_upl[(size_t)T_TOK * FF_PAD];
__device__ bf16  g_f1h[512 * 4 * D_MODEL],     g_f1l[512 * 4 * D_MODEL];
// transposed/split weights [N, Kp]
__device__ bf16 g_patchTh[1280 * PATCH_KP],              g_patchTl[1280 * PATCH_KP];
__device__ bf16 g_qkvTh [DEPTH * 3840 * 1280],           g_qkvTl [DEPTH * 3840 * 1280];
__device__ bf16 g_projTh[DEPTH * 1280 * 1280],           g_projTl[DEPTH * 1280 * 1280];
__device__ bf16 g_gateTh[(size_t)DEPTH * FF_PAD * 1280], g_gateTl[(size_t)DEPTH * FF_PAD * 1280];
__device__ bf16 g_upTh  [(size_t)DEPTH * FF_PAD * 1280], g_upTl  [(size_t)DEPTH * FF_PAD * 1280];
__device__ bf16 g_downTh[(size_t)DEPTH * 1280 * FF_PAD], g_downTl[(size_t)DEPTH * 1280 * FF_PAD];
__device__ bf16 g_fc1Th [5120 * 5120],                   g_fc1Tl [5120 * 5120];
__device__ bf16 g_fc2Th [3584 * 5120],                   g_fc2Tl [3584 * 5120];

// ---------------- conversion kernels ----------------
__global__ void conv_act(const float* __restrict__ X, bf16* __restrict__ Xh,
                         bf16* __restrict__ Xl, int M, int K, int Kp) {
    int idx = blockIdx.x * 256 + threadIdx.x;
    if (idx >= M * Kp) return;
    int m = idx / Kp, k = idx - m * Kp;
    float v = (k < K) ? X[(size_t)m * K + k] : 0.f;
    bf16 h = __float2bfloat16(v);
    Xh[idx] = h;
    Xl[idx] = __float2bfloat16(v - __bfloat162float(h));
}

__global__ void conv_wt_t(const float* __restrict__ B, bf16* __restrict__ Bth,
                          bf16* __restrict__ Btl, int K, int N, int Kp, int Np) {
    __shared__ float t[32][33];
    int kb = blockIdx.x * 32, nb = blockIdx.y * 32;
#pragma unroll
    for (int j = 0; j < 32; j += 8) {
        int k = kb + threadIdx.y + j, n = nb + threadIdx.x;
        t[threadIdx.y + j][threadIdx.x] = (k < K && n < N) ? B[(size_t)k * N + n] : 0.f;
    }
    __syncthreads();
#pragma unroll
    for (int j = 0; j < 32; j += 8) {
        int n = nb + threadIdx.y + j, k = kb + threadIdx.x;
        if (n < Np && k < Kp) {
            float v = t[threadIdx.x][threadIdx.y + j];
            bf16 h = __float2bfloat16(v);
            Bth[(size_t)n * Kp + k] = h;
            Btl[(size_t)n * Kp + k] = __float2bfloat16(v - __bfloat162float(h));
        }
    }
}

// ---------------- HMMA GEMM (split-bf16, 3 passes fused into k loop) ----------------
enum { EPI_NONE = 0, EPI_BIAS, EPI_BIAS_SILU, EPI_BIAS_RES, EPI_BIAS_MUL, EPI_BIAS_GELU };

// smem: 3 stages x (A 128x80B + B 128x80B) = 61440 bytes
#define ROWP 80
#define STAGE_BYTES (2 * 128 * ROWP)
#define GEMM_SMEM (3 * STAGE_BYTES)

template <int EPI, bool PAIR>
__global__ __launch_bounds__(256)
void gemm_mma(const bf16* __restrict__ Ah, const bf16* __restrict__ Al,
              const bf16* __restrict__ Bh, const bf16* __restrict__ Bl,
              const float* __restrict__ bias, const float* __restrict__ Rsrc,
              float* __restrict__ C, bf16* __restrict__ Ch, bf16* __restrict__ Cl,
              int Kp, int Nlog, int Nstride, int Rstride)
{
    extern __shared__ __align__(128) char smem[];
    const uint32_t sbase = smem_u32(smem);
    const int tid = threadIdx.x, lane = tid & 31, wid = tid >> 5;
    const int warp_m = wid >> 2, warp_n = wid & 3;     // 2 x 4 warps
    const int row0 = blockIdx.x * 128, col0 = blockIdx.y * 128;

    const int kc  = Kp >> 5;        // k32 chunks per pass
    const int nch = 3 * kc;
    const size_t rowB = (size_t)Kp * 2;

    // per-thread cp.async mapping: 2 segs per operand per stage
    const int ld_r  = tid >> 2;           // 0..63 (x2 with +64)
    const int ld_sg = (tid & 3) * 16;     // byte seg within 64B row

    auto loadChunk = [&](int c, int buf) {
        const int p = c / kc;
        const size_t kk = (size_t)(c - p * kc) * 64;   // byte offset in K
        const char* Ap = (const char*)(p == 2 ? Al : Ah) + (size_t)row0 * rowB + kk;
        const char* Bp = (const char*)(p == 1 ? Bl : Bh) + (size_t)col0 * rowB + kk;
        const uint32_t sA = sbase + buf * STAGE_BYTES;
        const uint32_t sB = sA + 128 * ROWP;
#pragma unroll
        for (int i = 0; i < 2; i++) {
            const int r = ld_r + i * 64;
            cp_async16(sA + r * ROWP + ld_sg, Ap + (size_t)r * rowB + ld_sg);
            cp_async16(sB + r * ROWP + ld_sg, Bp + (size_t)r * rowB + ld_sg);
        }
        CP_COMMIT();
    };

    float acc[4][4][4];
#pragma unroll
    for (int i = 0; i < 4; i++)
#pragma unroll
        for (int j = 0; j < 4; j++)
#pragma unroll
            for (int q = 0; q < 4; q++) acc[i][j][q] = 0.f;

    loadChunk(0, 0);
    loadChunk(1, 1);

    // ldmatrix lane addressing (conflict-free via 80B row pitch)
    const int a_row = warp_m * 64 + (lane & 15);
    const int a_seg = (lane >> 4);                      // 0/1 -> +8 cols
    const int b_row = warp_n * 32 + (lane & 7) + ((lane >> 4) << 3);
    const int b_seg = (lane >> 3) & 1;

    for (int c = 0; c < nch; c++) {
        if (c + 2 < nch) { CP_WAIT(1); } else { CP_WAIT(0); }
        __syncthreads();
        const int buf = c % 3;
        if (c + 2 < nch) loadChunk(c + 2, (c + 2) % 3);

        const uint32_t sA = sbase + buf * STAGE_BYTES;
        const uint32_t sB = sA + 128 * ROWP;

#pragma unroll
        for (int s = 0; s < 2; s++) {
            uint32_t a[4][4], b[2][4];
#pragma unroll
            for (int mi = 0; mi < 4; mi++)
                ldm_x4(a[mi][0], a[mi][1], a[mi][2], a[mi][3],
                       sA + (a_row + mi * 16) * ROWP + (s * 2 + a_seg) * 16);
#pragma unroll
            for (int j = 0; j < 2; j++)
                ldm_x4(b[j][0], b[j][1], b[j][2], b[j][3],
                       sB + (b_row + j * 16) * ROWP + (s * 2 + b_seg) * 16);
#pragma unroll
            for (int mi = 0; mi < 4; mi++)
#pragma unroll
                for (int ni = 0; ni < 4; ni++)
                    mma16816(acc[mi][ni], a[mi],
                             b[ni >> 1][(ni & 1) * 2], b[ni >> 1][(ni & 1) * 2 + 1]);
        }
        __syncthreads();
    }

    // ---------------- epilogue (register -> global) ----------------
    const int g = lane >> 2, tig = lane & 3;
#pragma unroll
    for (int mi = 0; mi < 4; mi++) {
#pragma unroll
        for (int half = 0; half < 2; half++) {
            const int r = row0 + warp_m * 64 + mi * 16 + g + half * 8;
#pragma unroll
            for (int ni = 0; ni < 4; ni++) {
                const int col = col0 + warp_n * 32 + ni * 8 + tig * 2;
                float v0 = acc[mi][ni][half * 2 + 0];
                float v1 = acc[mi][ni][half * 2 + 1];
                const bool ok = (col < Nlog);
                if (EPI != EPI_NONE && ok) {
                    const float2 bb = *(const float2*)(bias + col);
                    v0 += bb.x; v1 += bb.y;
                }
                if (EPI == EPI_BIAS_SILU) {
                    v0 = v0 / (1.f + __expf(-v0));
                    v1 = v1 / (1.f + __expf(-v1));
                }
                if (EPI == EPI_BIAS_GELU) {
                    v0 = 0.5f * v0 * (1.f + erff(v0 * 0.7071067811865475f));
                    v1 = 0.5f * v1 * (1.f + erff(v1 * 0.7071067811865475f));
                }
                if (EPI == EPI_BIAS_RES && ok) {
                    const float2 rr = *(const float2*)(Rsrc + (size_t)r * Rstride + col);
                    v0 += rr.x; v1 += rr.y;
                }
                if (EPI == EPI_BIAS_MUL) {
                    if (ok) {
                        const float2 rr = *(const float2*)(Rsrc + (size_t)r * Rstride + col);
                        v0 *= rr.x; v1 *= rr.y;
                    } else { v0 = 0.f; v1 = 0.f; }
                }
                if (PAIR) {
                    if (!ok && EPI != EPI_BIAS_MUL) { v0 = 0.f; v1 = 0.f; }
                    const bf16 h0 = __float2bfloat16(v0);
                    const bf16 h1 = __float2bfloat16(v1);
                    const bf16 l0 = __float2bfloat16(v0 - __bfloat162float(h0));
                    const bf16 l1 = __float2bfloat16(v1 - __bfloat162float(h1));
                    *(__nv_bfloat162*)(Ch + (size_t)r * Nstride + col) = __nv_bfloat162(h0, h1);
                    *(__nv_bfloat162*)(Cl + (size_t)r * Nstride + col) = __nv_bfloat162(l0, l1);
                } else if (ok) {
                    *(float2*)(C + (size_t)r * Nstride + col) = make_float2(v0, v1);
                }
            }
        }
    }
}

// ---------------- rmsnorm -> bf16 hi/lo ----------------
__global__ void rmsnorm_pair(const float* __restrict__ x, const float* __restrict__ s,
                             bf16* __restrict__ yh, bf16* __restrict__ yl)
{
    const int row = blockIdx.x;
    const float* xr = x + (size_t)row * D_MODEL;
    float sum = 0.f;
    for (int i = threadIdx.x; i < D_MODEL; i += 256) { float v = xr[i]; sum += v * v; }
#pragma unroll
    for (int o = 16; o; o >>= 1) sum += __shfl_xor_sync(~0u, sum, o);
    __shared__ float red[8];
    const int warp = threadIdx.x >> 5, lane = threadIdx.x & 31;
    if (lane == 0) red[warp] = sum;
    __syncthreads();
    if (warp == 0) {
        float v = (lane < 8) ? red[lane] : 0.f;
#pragma unroll
        for (int o = 4; o; o >>= 1) v += __shfl_xor_sync(~0u, v, o);
        if (lane == 0) red[0] = v;
    }
    __syncthreads();
    const float rinv = rsqrtf(red[0] * (1.f / D_MODEL) + EPS_RMS);
    for (int i = threadIdx.x; i < D_MODEL; i += 256) {
        float v = xr[i] * s[i] * rinv;
        bf16 h = __float2bfloat16(v);
        yh[(size_t)row * D_MODEL + i] = h;
        yl[(size_t)row * D_MODEL + i] = __float2bfloat16(v - __bfloat162float(h));
    }
}

// ---------------- RoPE ----------------
__global__ void rope_kernel(float* __restrict__ qkv, const float* __restrict__ rot)
{
    const int per = T_TOK * H_HEADS * HALF;
    int idx = blockIdx.x * blockDim.x + threadIdx.x;
    if (idx >= 2 * per) return;
    const int which = (idx >= per) ? 1 : 0;
    int rem = idx - which * per;
    const int t = rem / (H_HEADS * HALF);
    const int r2 = rem % (H_HEADS * HALF);
    const int hh = r2 / HALF, d = r2 % HALF;
    float s, c;
    sincosf(rot[t * HALF + d], &s, &c);
    float* p = qkv + (size_t)t * (3 * D_MODEL) + which * D_MODEL + hh * HD + d;
    const float re = p[0], im = p[HALF];
    p[0] = re * c - im * s;
    p[HALF] = re * s + im * c;
}

// ---------------- windowed attention -> bf16 hi/lo out ----------------
#define ATT_SMEM ((64 * 80 + 64 * 81 + 64 * 80 + 8 * 64) * 4)

__global__ void attn_kernel(const float* __restrict__ qkv, bf16* __restrict__ oh,
                            bf16* __restrict__ ol)
{
    extern __shared__ float sm[];
    float* qs = sm;
    float* ks = qs + 64 * 80;
    float* vs = ks + 64 * 81;
    float* pr = vs + 64 * 80;
    const int w = blockIdx.x, hh = blockIdx.y;
    const int tid = threadIdx.x, lane = tid & 31, warp = tid >> 5;
    const size_t base = (size_t)w * WIN * (3 * D_MODEL) + hh * HD;

    for (int idx = tid; idx < WIN * HD; idx += 256) {
        const int t = idx / HD, d = idx % HD;
        const size_t g = base + (size_t)t * (3 * D_MODEL) + d;
        qs[t * 80 + d] = qkv[g];
        ks[t * 81 + d] = qkv[g + D_MODEL];
        vs[t * 80 + d] = qkv[g + 2 * D_MODEL];
    }
    __syncthreads();

    for (int row = warp; row < WIN; row += 8) {
        const float* qr = qs + row * 80;
        const float* k0 = ks + lane * 81;
        const float* k1 = ks + (lane + 32) * 81;
        float s0 = 0.f, s1 = 0.f;
#pragma unroll
        for (int d = 0; d < HD; d++) { const float q = qr[d]; s0 += q * k0[d]; s1 += q * k1[d]; }
        s0 *= ATT_SCALE; s1 *= ATT_SCALE;
        float mx = fmaxf(s0, s1);
#pragma unroll
        for (int o = 16; o; o >>= 1) mx = fmaxf(mx, __shfl_xor_sync(~0u, mx, o));
        const float e0 = __expf(s0 - mx), e1 = __expf(s1 - mx);
        float sum = e0 + e1;
#pragma unroll
        for (int o = 16; o; o >>= 1) sum += __shfl_xor_sync(~0u, sum, o);
        const float inv = 1.f / sum;
        pr[warp * 64 + lane] = e0 * inv;
        pr[warp * 64 + lane + 32] = e1 * inv;
        __syncwarp();
        float o0 = 0.f, o1 = 0.f, o2 = 0.f;
#pragma unroll 4
        for (int j = 0; j < WIN; j++) {
            const float p = pr[warp * 64 + j];
            const float* vr = vs + j * 80;
            o0 += p * vr[lane];
            o1 += p * vr[lane + 32];
            if (lane < 16) o2 += p * vr[lane + 64];
        }
        const size_t ob = (size_t)(w * WIN + row) * D_MODEL + hh * HD;
        bf16 h;
        h = __float2bfloat16(o0); oh[ob + lane] = h;
        ol[ob + lane] = __float2bfloat16(o0 - __bfloat162float(h));
        h = __float2bfloat16(o1); oh[ob + lane + 32] = h;
        ol[ob + lane + 32] = __float2bfloat16(o1 - __bfloat162float(h));
        if (lane < 16) {
            h = __float2bfloat16(o2); oh[ob + lane + 64] = h;
            ol[ob + lane + 64] = __float2bfloat16(o2 - __bfloat162float(h));
        }
        __syncwarp();
    }
}

// ---------------- host ----------------
static inline dim3 tg(int K, int N) { return dim3((K + 31) / 32, (N + 31) / 32); }

extern "C" void kernel_launch(void* const* d_in, const int* in_sizes, int n_in,
                              void* d_out, int out_size)
{
    const float* x      = (const float*)d_in[0];
    const float* rot    = (const float*)d_in[1];
    const float* patchw = (const float*)d_in[3];
    const float* qkvw   = (const float*)d_in[4];
    const float* qkvb   = (const float*)d_in[5];
    const float* projw  = (const float*)d_in[6];
    const float* projb  = (const float*)d_in[7];
    const float* n1s    = (const float*)d_in[8];
    const float* n2s    = (const float*)d_in[9];
    const float* gw     = (const float*)d_in[10];
    const float* gb     = (const float*)d_in[11];
    const float* uw     = (const float*)d_in[12];
    const float* ub     = (const float*)d_in[13];
    const float* dw     = (const float*)d_in[14];
    const float* db     = (const float*)d_in[15];
    const float* lnq    = (const float*)d_in[16];
    const float* f1w    = (const float*)d_in[17];
    const float* f1b    = (const float*)d_in[18];
    const float* f2w    = (const float*)d_in[19];
    const float* f2b    = (const float*)d_in[20];
    float* out = (float*)d_out;

    float *h, *qkv, *gate;
    bf16 *xh, *xl, *nh, *nl, *ath, *atl, *uph, *upl, *f1h, *f1l;
    bf16 *patchTh, *patchTl, *qkvTh, *qkvTl, *projTh, *projTl;
    bf16 *gateTh, *gateTl, *upTh, *upTl, *downTh, *downTl, *fc1Th, *fc1Tl, *fc2Th, *fc2Tl;
    cudaGetSymbolAddress((void**)&h, g_h);       cudaGetSymbolAddress((void**)&qkv, g_qkv);
    cudaGetSymbolAddress((void**)&gate, g_gate);
    cudaGetSymbolAddress((void**)&xh, g_xh);     cudaGetSymbolAddress((void**)&xl, g_xl);
    cudaGetSymbolAddress((void**)&nh, g_nh);     cudaGetSymbolAddress((void**)&nl, g_nl);
    cudaGetSymbolAddress((void**)&ath, g_ath);   cudaGetSymbolAddress((void**)&atl, g_atl);
    cudaGetSymbolAddress((void**)&uph, g_uph);   cudaGetSymbolAddress((void**)&upl, g_upl);
    cudaGetSymbolAddress((void**)&f1h, g_f1h);   cudaGetSymbolAddress((void**)&f1l, g_f1l);
    cudaGetSymbolAddress((void**)&patchTh, g_patchTh); cudaGetSymbolAddress((void**)&patchTl, g_patchTl);
    cudaGetSymbolAddress((void**)&qkvTh, g_qkvTh);     cudaGetSymbolAddress((void**)&qkvTl, g_qkvTl);
    cudaGetSymbolAddress((void**)&projTh, g_projTh);   cudaGetSymbolAddress((void**)&projTl, g_projTl);
    cudaGetSymbolAddress((void**)&gateTh, g_gateTh);   cudaGetSymbolAddress((void**)&gateTl, g_gateTl);
    cudaGetSymbolAddress((void**)&upTh, g_upTh);       cudaGetSymbolAddress((void**)&upTl, g_upTl);
    cudaGetSymbolAddress((void**)&downTh, g_downTh);   cudaGetSymbolAddress((void**)&downTl, g_downTl);
    cudaGetSymbolAddress((void**)&fc1Th, g_fc1Th);     cudaGetSymbolAddress((void**)&fc1Tl, g_fc1Tl);
    cudaGetSymbolAddress((void**)&fc2Th, g_fc2Th);     cudaGetSymbolAddress((void**)&fc2Tl, g_fc2Tl);

    cudaFuncSetAttribute(attn_kernel, cudaFuncAttributeMaxDynamicSharedMemorySize, ATT_SMEM);
    cudaFuncSetAttribute(gemm_mma<EPI_NONE, false>, cudaFuncAttributeMaxDynamicSharedMemorySize, GEMM_SMEM);
    cudaFuncSetAttribute(gemm_mma<EPI_BIAS, false>, cudaFuncAttributeMaxDynamicSharedMemorySize, GEMM_SMEM);
    cudaFuncSetAttribute(gemm_mma<EPI_BIAS_RES, false>, cudaFuncAttributeMaxDynamicSharedMemorySize, GEMM_SMEM);
    cudaFuncSetAttribute(gemm_mma<EPI_BIAS_SILU, false>, cudaFuncAttributeMaxDynamicSharedMemorySize, GEMM_SMEM);
    cudaFuncSetAttribute(gemm_mma<EPI_BIAS_MUL, true>, cudaFuncAttributeMaxDynamicSharedMemorySize, GEMM_SMEM);
    cudaFuncSetAttribute(gemm_mma<EPI_BIAS_GELU, true>, cudaFuncAttributeMaxDynamicSharedMemorySize, GEMM_SMEM);

    // ---- input/weight conversion + transpose ----
    conv_act<<<(T_TOK * PATCH_KP + 255) / 256, 256>>>(x, xh, xl, T_TOK, PATCH_IN, PATCH_KP);
    conv_wt_t<<<tg(PATCH_KP, 1280), dim3(32, 8)>>>(patchw, patchTh, patchTl, PATCH_IN, 1280, PATCH_KP, 1280);
    for (int l = 0; l < DEPTH; l++) {
        conv_wt_t<<<tg(1280, 3840), dim3(32, 8)>>>(qkvw + (size_t)l * 1280 * 3840,
            qkvTh + (size_t)l * 3840 * 1280, qkvTl + (size_t)l * 3840 * 1280, 1280, 3840, 1280, 3840);
        conv_wt_t<<<tg(1280, 1280), dim3(32, 8)>>>(projw + (size_t)l * 1280 * 1280,
            projTh + (size_t)l * 1280 * 1280, projTl + (size_t)l * 1280 * 1280, 1280, 1280, 1280, 1280);
        conv_wt_t<<<tg(1280, FF_PAD), dim3(32, 8)>>>(gw + (size_t)l * 1280 * FF_DIM,
            gateTh + (size_t)l * FF_PAD * 1280, gateTl + (size_t)l * FF_PAD * 1280, 1280, FF_DIM, 1280, FF_PAD);
        conv_wt_t<<<tg(1280, FF_PAD), dim3(32, 8)>>>(uw + (size_t)l * 1280 * FF_DIM,
            upTh + (size_t)l * FF_PAD * 1280, upTl + (size_t)l * FF_PAD * 1280, 1280, FF_DIM, 1280, FF_PAD);
        conv_wt_t<<<tg(FF_PAD, 1280), dim3(32, 8)>>>(dw + (size_t)l * FF_DIM * 1280,
            downTh + (size_t)l * 1280 * FF_PAD, downTl + (size_t)l * 1280 * FF_PAD, FF_DIM, 1280, FF_PAD, 1280);
    }
    conv_wt_t<<<tg(5120, 5120), dim3(32, 8)>>>(f1w, fc1Th, fc1Tl, 5120, 5120, 5120, 5120);
    conv_wt_t<<<tg(5120, 3584), dim3(32, 8)>>>(f2w, fc2Th, fc2Tl, 5120, 3584, 5120, 3584);

    // ---- patch embed ----
    gemm_mma<EPI_NONE, false><<<dim3(16, 10), 256, GEMM_SMEM>>>(
        xh, xl, patchTh, patchTl, nullptr, nullptr, h, nullptr, nullptr,
        PATCH_KP, 1280, 1280, 0);

    for (int l = 0; l < DEPTH; l++) {
        const size_t lD = (size_t)l * D_MODEL;
        rmsnorm_pair<<<T_TOK, 256>>>(h, n1s + lD, nh, nl);
        gemm_mma<EPI_BIAS, false><<<dim3(16, 30), 256, GEMM_SMEM>>>(
            nh, nl, qkvTh + (size_t)l * 3840 * 1280, qkvTl + (size_t)l * 3840 * 1280,
            qkvb + (size_t)l * 3840, nullptr, qkv, nullptr, nullptr, 1280, 3840, 3840, 0);
        rope_kernel<<<(2 * T_TOK * H_HEADS * HALF + 255) / 256, 256>>>(qkv, rot);
        attn_kernel<<<dim3(NWIN, H_HEADS), 256, ATT_SMEM>>>(qkv, ath, atl);
        gemm_mma<EPI_BIAS_RES, false><<<dim3(16, 10), 256, GEMM_SMEM>>>(
            ath, atl, projTh + (size_t)l * 1280 * 1280, projTl + (size_t)l * 1280 * 1280,
            projb + lD, h, h, nullptr, nullptr, 1280, 1280, 1280, 1280);
        rmsnorm_pair<<<T_TOK, 256>>>(h, n2s + lD, nh, nl);
        gemm_mma<EPI_BIAS_SILU, false><<<dim3(16, 27), 256, GEMM_SMEM>>>(
            nh, nl, gateTh + (size_t)l * FF_PAD * 1280, gateTl + (size_t)l * FF_PAD * 1280,
            gb + (size_t)l * FF_DIM, nullptr, gate, nullptr, nullptr, 1280, FF_DIM, FF_DIM, 0);
        gemm_mma<EPI_BIAS_MUL, true><<<dim3(16, 27), 256, GEMM_SMEM>>>(
            nh, nl, upTh + (size_t)l * FF_PAD * 1280, upTl + (size_t)l * FF_PAD * 1280,
            ub + (size_t)l * FF_DIM, gate, nullptr, uph, upl, 1280, FF_DIM, FF_PAD, FF_DIM);
        gemm_mma<EPI_BIAS_RES, false><<<dim3(16, 10), 256, GEMM_SMEM>>>(
            uph, upl, downTh + (size_t)l * 1280 * FF_PAD, downTl + (size_t)l * 1280 * FF_PAD,
            db + lD, h, h, nullptr, nullptr, FF_PAD, 1280, 1280, 1280);
    }

    rmsnorm_pair<<<T_TOK, 256>>>(h, lnq, nh, nl);
    gemm_mma<EPI_BIAS_GELU, true><<<dim3(4, 40), 256, GEMM_SMEM>>>(
        nh, nl, fc1Th, fc1Tl, f1b, nullptr, nullptr, f1h, f1l, 5120, 5120, 5120, 0);
    gemm_mma<EPI_BIAS, false><<<dim3(4, 28), 256, GEMM_SMEM>>>(
        f1h, f1l, fc2Th, fc2Tl, f2b, nullptr, out, nullptr, nullptr, 5120, 3584, 3584, 0);
}

// round 4
// speedup vs baseline: 3.3167x; 1.1205x over previous
#include <cuda_runtime.h>
#include <cuda_bf16.h>
#include <math.h>
#include <stdint.h>

// ---------------- problem constants ----------------
#define T_TOK   2048
#define D_MODEL 1280
#define H_HEADS 16
#define HD      80
#define HALF    40
#define FF_DIM  3420
#define FF_PAD  3456
#define DEPTH   4
#define OUT_DIM 3584
#define PATCH_IN 1176
#define PATCH_KP 1216
#define WIN     64
#define NWIN    (T_TOK / WIN)
#define EPS_RMS 1e-6f
#define ATT_SCALE 0.1118033988749895f

typedef __nv_bfloat16 bf16;

// ---------------- helpers ----------------
__device__ __forceinline__ uint32_t smem_u32(const void* p) {
    uint32_t a;
    asm("{ .reg .u64 t; cvta.to.shared.u64 t, %1; cvt.u32.u64 %0, t; }" : "=r"(a) : "l"(p));
    return a;
}
__device__ __forceinline__ void cp_async16(uint32_t s, const void* g) {
    asm volatile("cp.async.cg.shared.global [%0], [%1], 16;" :: "r"(s), "l"(g));
}
#define CP_COMMIT() asm volatile("cp.async.commit_group;" ::: "memory")
#define CP_WAIT(n)  asm volatile("cp.async.wait_group %0;" :: "n"(n) : "memory")

__device__ __forceinline__ void ldm_x4(uint32_t& r0, uint32_t& r1, uint32_t& r2,
                                       uint32_t& r3, uint32_t addr) {
    asm volatile("ldmatrix.sync.aligned.m8n8.x4.shared.b16 {%0,%1,%2,%3}, [%4];"
                 : "=r"(r0), "=r"(r1), "=r"(r2), "=r"(r3) : "r"(addr));
}
__device__ __forceinline__ void mma16816(float* d, const uint32_t* a,
                                         uint32_t b0, uint32_t b1) {
    asm volatile("mma.sync.aligned.m16n8k16.row.col.f32.bf16.bf16.f32 "
                 "{%0,%1,%2,%3}, {%4,%5,%6,%7}, {%8,%9}, {%0,%1,%2,%3};"
                 : "+f"(d[0]), "+f"(d[1]), "+f"(d[2]), "+f"(d[3])
                 : "r"(a[0]), "r"(a[1]), "r"(a[2]), "r"(a[3]), "r"(b0), "r"(b1));
}

// ---------------- scratch ----------------
__device__ float g_h   [T_TOK * D_MODEL];
__device__ float g_qkv [T_TOK * 3 * D_MODEL];
__device__ float g_gate[(size_t)T_TOK * FF_DIM];
__device__ bf16  g_xh [T_TOK * PATCH_KP],      g_xl [T_TOK * PATCH_KP];
__device__ bf16  g_nh [T_TOK * D_MODEL],       g_nl [T_TOK * D_MODEL];
__device__ bf16  g_ath[T_TOK * D_MODEL],       g_atl[T_TOK * D_MODEL];
__device__ bf16  g_uph[(size_t)T_TOK * FF_PAD], g_upl[(size_t)T_TOK * FF_PAD];
__device__ bf16  g_f1h[512 * 4 * D_MODEL],     g_f1l[512 * 4 * D_MODEL];
// transposed/split weights [N, Kp]
__device__ bf16 g_patchTh[1280 * PATCH_KP],              g_patchTl[1280 * PATCH_KP];
__device__ bf16 g_qkvTh [DEPTH * 3840 * 1280],           g_qkvTl [DEPTH * 3840 * 1280];
__device__ bf16 g_projTh[DEPTH * 1280 * 1280],           g_projTl[DEPTH * 1280 * 1280];
__device__ bf16 g_gateTh[(size_t)DEPTH * FF_PAD * 1280], g_gateTl[(size_t)DEPTH * FF_PAD * 1280];
__device__ bf16 g_upTh  [(size_t)DEPTH * FF_PAD * 1280], g_upTl  [(size_t)DEPTH * FF_PAD * 1280];
__device__ bf16 g_downTh[(size_t)DEPTH * 1280 * FF_PAD], g_downTl[(size_t)DEPTH * 1280 * FF_PAD];
__device__ bf16 g_fc1Th [5120 * 5120],                   g_fc1Tl [5120 * 5120];
__device__ bf16 g_fc2Th [3584 * 5120],                   g_fc2Tl [3584 * 5120];

// ---------------- activation split ----------------
__global__ void conv_act(const float* __restrict__ X, bf16* __restrict__ Xh,
                         bf16* __restrict__ Xl, int M, int K, int Kp) {
    int idx = blockIdx.x * 256 + threadIdx.x;
    if (idx >= M * Kp) return;
    int m = idx / Kp, k = idx - m * Kp;
    float v = (k < K) ? X[(size_t)m * K + k] : 0.f;
    bf16 h = __float2bfloat16(v);
    Xh[idx] = h;
    Xl[idx] = __float2bfloat16(v - __bfloat162float(h));
}

// ---------------- batched weight transpose+split (all matrices, one launch) ----------------
#define NSEG 23
struct Seg { const float* s; bf16* dh; bf16* dl; int K, N, Kp, tile0, tilesX; };
struct ConvTable { Seg seg[NSEG]; };

__global__ void conv_all(ConvTable tb) {
    __shared__ float t[32][33];
    const int tile = blockIdx.x;
    int si = 0;
#pragma unroll
    for (int i = 1; i < NSEG; i++) si += (tb.seg[i].tile0 <= tile);
    const Seg sg = tb.seg[si];
    const int lt = tile - sg.tile0;
    const int kb = (lt % sg.tilesX) * 32;
    const int nb = (lt / sg.tilesX) * 32;
#pragma unroll
    for (int j = 0; j < 32; j += 8) {
        int k = kb + threadIdx.y + j, n = nb + threadIdx.x;
        t[threadIdx.y + j][threadIdx.x] =
            (k < sg.K && n < sg.N) ? sg.s[(size_t)k * sg.N + n] : 0.f;
    }
    __syncthreads();
#pragma unroll
    for (int j = 0; j < 32; j += 8) {
        int n = nb + threadIdx.y + j, k = kb + threadIdx.x;
        if (k < sg.Kp) {
            float v = t[threadIdx.x][threadIdx.y + j];
            bf16 h = __float2bfloat16(v);
            sg.dh[(size_t)n * sg.Kp + k] = h;
            sg.dl[(size_t)n * sg.Kp + k] = __float2bfloat16(v - __bfloat162float(h));
        }
    }
}

// ---------------- HMMA GEMM (split-bf16, 3 passes fused into k loop) ----------------
enum { EPI_NONE = 0, EPI_BIAS, EPI_BIAS_SILU, EPI_BIAS_RES, EPI_BIAS_MUL, EPI_BIAS_GELU };

#define ROWP 80
#define STAGE_BYTES (2 * 128 * ROWP)
#define NSTAGE 4
#define GEMM_SMEM (NSTAGE * STAGE_BYTES)

template <int EPI, bool PAIR>
__global__ __launch_bounds__(256, 2)
void gemm_mma(const bf16* __restrict__ Ah, const bf16* __restrict__ Al,
              const bf16* __restrict__ Bh, const bf16* __restrict__ Bl,
              const float* __restrict__ bias, const float* __restrict__ Rsrc,
              float* __restrict__ C, bf16* __restrict__ Ch, bf16* __restrict__ Cl,
              int Kp, int Nlog, int Nstride, int Rstride)
{
    extern __shared__ __align__(128) char smem[];
    const uint32_t sbase = smem_u32(smem);
    const int tid = threadIdx.x, lane = tid & 31, wid = tid >> 5;
    const int warp_m = wid >> 2, warp_n = wid & 3;     // 2 x 4 warps
    const int row0 = blockIdx.x * 128, col0 = blockIdx.y * 128;

    const int kc  = Kp >> 5;
    const int nch = 3 * kc;
    const size_t rowB = (size_t)Kp * 2;

    const int ld_r  = tid >> 2;
    const int ld_sg = (tid & 3) * 16;

    auto loadChunk = [&](int c, int buf) {
        const int p = c / kc;
        const size_t kk = (size_t)(c - p * kc) * 64;
        const char* Ap = (const char*)(p == 2 ? Al : Ah) + (size_t)row0 * rowB + kk;
        const char* Bp = (const char*)(p == 1 ? Bl : Bh) + (size_t)col0 * rowB + kk;
        const uint32_t sA = sbase + buf * STAGE_BYTES;
        const uint32_t sB = sA + 128 * ROWP;
#pragma unroll
        for (int i = 0; i < 2; i++) {
            const int r = ld_r + i * 64;
            cp_async16(sA + r * ROWP + ld_sg, Ap + (size_t)r * rowB + ld_sg);
            cp_async16(sB + r * ROWP + ld_sg, Bp + (size_t)r * rowB + ld_sg);
        }
        CP_COMMIT();
    };

    float acc[4][4][4];
#pragma unroll
    for (int i = 0; i < 4; i++)
#pragma unroll
        for (int j = 0; j < 4; j++)
#pragma unroll
            for (int q = 0; q < 4; q++) acc[i][j][q] = 0.f;

    loadChunk(0, 0);
    loadChunk(1, 1);
    loadChunk(2, 2);

    const int a_row = warp_m * 64 + (lane & 15);
    const int a_seg = (lane >> 4);
    const int b_row = warp_n * 32 + (lane & 7) + ((lane >> 4) << 3);
    const int b_seg = (lane >> 3) & 1;

    for (int c = 0; c < nch; c++) {
        if (c + 3 <= nch)      { CP_WAIT(2); }
        else if (c + 2 == nch) { CP_WAIT(1); }
        else                   { CP_WAIT(0); }
        __syncthreads();
        if (c + 3 < nch) loadChunk(c + 3, (c + 3) & (NSTAGE - 1));

        const int buf = c & (NSTAGE - 1);
        const uint32_t sA = sbase + buf * STAGE_BYTES;
        const uint32_t sB = sA + 128 * ROWP;

#pragma unroll
        for (int s = 0; s < 2; s++) {
            uint32_t a[4][4], b[2][4];
#pragma unroll
            for (int mi = 0; mi < 4; mi++)
                ldm_x4(a[mi][0], a[mi][1], a[mi][2], a[mi][3],
                       sA + (a_row + mi * 16) * ROWP + (s * 2 + a_seg) * 16);
#pragma unroll
            for (int j = 0; j < 2; j++)
                ldm_x4(b[j][0], b[j][1], b[j][2], b[j][3],
                       sB + (b_row + j * 16) * ROWP + (s * 2 + b_seg) * 16);
#pragma unroll
            for (int mi = 0; mi < 4; mi++)
#pragma unroll
                for (int ni = 0; ni < 4; ni++)
                    mma16816(acc[mi][ni], a[mi],
                             b[ni >> 1][(ni & 1) * 2], b[ni >> 1][(ni & 1) * 2 + 1]);
        }
    }

    // ---------------- epilogue ----------------
    const int g = lane >> 2, tig = lane & 3;
#pragma unroll
    for (int mi = 0; mi < 4; mi++) {
#pragma unroll
        for (int half = 0; half < 2; half++) {
            const int r = row0 + warp_m * 64 + mi * 16 + g + half * 8;
#pragma unroll
            for (int ni = 0; ni < 4; ni++) {
                const int col = col0 + warp_n * 32 + ni * 8 + tig * 2;
                float v0 = acc[mi][ni][half * 2 + 0];
                float v1 = acc[mi][ni][half * 2 + 1];
                const bool ok = (col < Nlog);
                if (EPI != EPI_NONE && ok) {
                    const float2 bb = *(const float2*)(bias + col);
                    v0 += bb.x; v1 += bb.y;
                }
                if (EPI == EPI_BIAS_SILU) {
                    v0 = v0 / (1.f + __expf(-v0));
                    v1 = v1 / (1.f + __expf(-v1));
                }
                if (EPI == EPI_BIAS_GELU) {
                    v0 = 0.5f * v0 * (1.f + erff(v0 * 0.7071067811865475f));
                    v1 = 0.5f * v1 * (1.f + erff(v1 * 0.7071067811865475f));
                }
                if (EPI == EPI_BIAS_RES && ok) {
                    const float2 rr = *(const float2*)(Rsrc + (size_t)r * Rstride + col);
                    v0 += rr.x; v1 += rr.y;
                }
                if (EPI == EPI_BIAS_MUL) {
                    if (ok) {
                        const float2 rr = *(const float2*)(Rsrc + (size_t)r * Rstride + col);
                        v0 *= rr.x; v1 *= rr.y;
                    } else { v0 = 0.f; v1 = 0.f; }
                }
                if (PAIR) {
                    if (!ok && EPI != EPI_BIAS_MUL) { v0 = 0.f; v1 = 0.f; }
                    const bf16 h0 = __float2bfloat16(v0);
                    const bf16 h1 = __float2bfloat16(v1);
                    const bf16 l0 = __float2bfloat16(v0 - __bfloat162float(h0));
                    const bf16 l1 = __float2bfloat16(v1 - __bfloat162float(h1));
                    *(__nv_bfloat162*)(Ch + (size_t)r * Nstride + col) = __nv_bfloat162(h0, h1);
                    *(__nv_bfloat162*)(Cl + (size_t)r * Nstride + col) = __nv_bfloat162(l0, l1);
                } else if (ok) {
                    *(float2*)(C + (size_t)r * Nstride + col) = make_float2(v0, v1);
                }
            }
        }
    }
}

// ---------------- rmsnorm -> bf16 hi/lo ----------------
__global__ void rmsnorm_pair(const float* __restrict__ x, const float* __restrict__ s,
                             bf16* __restrict__ yh, bf16* __restrict__ yl)
{
    const int row = blockIdx.x;
    const float* xr = x + (size_t)row * D_MODEL;
    float sum = 0.f;
    for (int i = threadIdx.x; i < D_MODEL; i += 256) { float v = xr[i]; sum += v * v; }
#pragma unroll
    for (int o = 16; o; o >>= 1) sum += __shfl_xor_sync(~0u, sum, o);
    __shared__ float red[8];
    const int warp = threadIdx.x >> 5, lane = threadIdx.x & 31;
    if (lane == 0) red[warp] = sum;
    __syncthreads();
    if (warp == 0) {
        float v = (lane < 8) ? red[lane] : 0.f;
#pragma unroll
        for (int o = 4; o; o >>= 1) v += __shfl_xor_sync(~0u, v, o);
        if (lane == 0) red[0] = v;
    }
    __syncthreads();
    const float rinv = rsqrtf(red[0] * (1.f / D_MODEL) + EPS_RMS);
    for (int i = threadIdx.x; i < D_MODEL; i += 256) {
        float v = xr[i] * s[i] * rinv;
        bf16 h = __float2bfloat16(v);
        yh[(size_t)row * D_MODEL + i] = h;
        yl[(size_t)row * D_MODEL + i] = __float2bfloat16(v - __bfloat162float(h));
    }
}

// ---------------- windowed attention with fused RoPE -> bf16 hi/lo out ----------------
#define ATT_SMEM ((64 * 80 + 64 * 81 + 64 * 80 + 8 * 64) * 4)

__global__ void attn_kernel(const float* __restrict__ qkv, const float* __restrict__ rot,
                            bf16* __restrict__ oh, bf16* __restrict__ ol)
{
    extern __shared__ float sm[];
    float* qs = sm;
    float* ks = qs + 64 * 80;
    float* vs = ks + 64 * 81;
    float* pr = vs + 64 * 80;
    const int w = blockIdx.x, hh = blockIdx.y;
    const int tid = threadIdx.x, lane = tid & 31, warp = tid >> 5;
    const size_t base = (size_t)w * WIN * (3 * D_MODEL) + hh * HD;

    // load q,k with RoPE applied on the fly
    for (int idx = tid; idx < WIN * HALF; idx += 256) {
        const int t = idx / HALF, d = idx % HALF;
        float s, c;
        sincosf(rot[(w * WIN + t) * HALF + d], &s, &c);
        const size_t g = base + (size_t)t * (3 * D_MODEL) + d;
        const float qre = qkv[g],          qim = qkv[g + HALF];
        const float kre = qkv[g + D_MODEL], kim = qkv[g + D_MODEL + HALF];
        qs[t * 80 + d]        = qre * c - qim * s;
        qs[t * 80 + d + HALF] = qre * s + qim * c;
        ks[t * 81 + d]        = kre * c - kim * s;
        ks[t * 81 + d + HALF] = kre * s + kim * c;
    }
    for (int idx = tid; idx < WIN * HD; idx += 256) {
        const int t = idx / HD, d = idx % HD;
        vs[t * 80 + d] = qkv[base + (size_t)t * (3 * D_MODEL) + 2 * D_MODEL + d];
    }
    __syncthreads();

    for (int row = warp; row < WIN; row += 8) {
        const float* qr = qs + row * 80;
        const float* k0 = ks + lane * 81;
        const float* k1 = ks + (lane + 32) * 81;
        float s0 = 0.f, s1 = 0.f;
#pragma unroll
        for (int d = 0; d < HD; d++) { const float q = qr[d]; s0 += q * k0[d]; s1 += q * k1[d]; }
        s0 *= ATT_SCALE; s1 *= ATT_SCALE;
        float mx = fmaxf(s0, s1);
#pragma unroll
        for (int o = 16; o; o >>= 1) mx = fmaxf(mx, __shfl_xor_sync(~0u, mx, o));
        const float e0 = __expf(s0 - mx), e1 = __expf(s1 - mx);
        float sum = e0 + e1;
#pragma unroll
        for (int o = 16; o; o >>= 1) sum += __shfl_xor_sync(~0u, sum, o);
        const float inv = 1.f / sum;
        pr[warp * 64 + lane] = e0 * inv;
        pr[warp * 64 + lane + 32] = e1 * inv;
        __syncwarp();
        float o0 = 0.f, o1 = 0.f, o2 = 0.f;
#pragma unroll 4
        for (int j = 0; j < WIN; j++) {
            const float p = pr[warp * 64 + j];
            const float* vr = vs + j * 80;
            o0 += p * vr[lane];
            o1 += p * vr[lane + 32];
            if (lane < 16) o2 += p * vr[lane + 64];
        }
        const size_t ob = (size_t)(w * WIN + row) * D_MODEL + hh * HD;
        bf16 h;
        h = __float2bfloat16(o0); oh[ob + lane] = h;
        ol[ob + lane] = __float2bfloat16(o0 - __bfloat162float(h));
        h = __float2bfloat16(o1); oh[ob + lane + 32] = h;
        ol[ob + lane + 32] = __float2bfloat16(o1 - __bfloat162float(h));
        if (lane < 16) {
            h = __float2bfloat16(o2); oh[ob + lane + 64] = h;
            ol[ob + lane + 64] = __float2bfloat16(o2 - __bfloat162float(h));
        }
        __syncwarp();
    }
}

// ---------------- host ----------------
extern "C" void kernel_launch(void* const* d_in, const int* in_sizes, int n_in,
                              void* d_out, int out_size)
{
    const float* x      = (const float*)d_in[0];
    const float* rot    = (const float*)d_in[1];
    const float* patchw = (const float*)d_in[3];
    const float* qkvw   = (const float*)d_in[4];
    const float* qkvb   = (const float*)d_in[5];
    const float* projw  = (const float*)d_in[6];
    const float* projb  = (const float*)d_in[7];
    const float* n1s    = (const float*)d_in[8];
    const float* n2s    = (const float*)d_in[9];
    const float* gw     = (const float*)d_in[10];
    const float* gb     = (const float*)d_in[11];
    const float* uw     = (const float*)d_in[12];
    const float* ub     = (const float*)d_in[13];
    const float* dw     = (const float*)d_in[14];
    const float* db     = (const float*)d_in[15];
    const float* lnq    = (const float*)d_in[16];
    const float* f1w    = (const float*)d_in[17];
    const float* f1b    = (const float*)d_in[18];
    const float* f2w    = (const float*)d_in[19];
    const float* f2b    = (const float*)d_in[20];
    float* out = (float*)d_out;

    float *h, *qkv, *gate;
    bf16 *xh, *xl, *nh, *nl, *ath, *atl, *uph, *upl, *f1h, *f1l;
    bf16 *patchTh, *patchTl, *qkvTh, *qkvTl, *projTh, *projTl;
    bf16 *gateTh, *gateTl, *upTh, *upTl, *downTh, *downTl, *fc1Th, *fc1Tl, *fc2Th, *fc2Tl;
    cudaGetSymbolAddress((void**)&h, g_h);       cudaGetSymbolAddress((void**)&qkv, g_qkv);
    cudaGetSymbolAddress((void**)&gate, g_gate);
    cudaGetSymbolAddress((void**)&xh, g_xh);     cudaGetSymbolAddress((void**)&xl, g_xl);
    cudaGetSymbolAddress((void**)&nh, g_nh);     cudaGetSymbolAddress((void**)&nl, g_nl);
    cudaGetSymbolAddress((void**)&ath, g_ath);   cudaGetSymbolAddress((void**)&atl, g_atl);
    cudaGetSymbolAddress((void**)&uph, g_uph);   cudaGetSymbolAddress((void**)&upl, g_upl);
    cudaGetSymbolAddress((void**)&f1h, g_f1h);   cudaGetSymbolAddress((void**)&f1l, g_f1l);
    cudaGetSymbolAddress((void**)&patchTh, g_patchTh); cudaGetSymbolAddress((void**)&patchTl, g_patchTl);
    cudaGetSymbolAddress((void**)&qkvTh, g_qkvTh);     cudaGetSymbolAddress((void**)&qkvTl, g_qkvTl);
    cudaGetSymbolAddress((void**)&projTh, g_projTh);   cudaGetSymbolAddress((void**)&projTl, g_projTl);
    cudaGetSymbolAddress((void**)&gateTh, g_gateTh);   cudaGetSymbolAddress((void**)&gateTl, g_gateTl);
    cudaGetSymbolAddress((void**)&upTh, g_upTh);       cudaGetSymbolAddress((void**)&upTl, g_upTl);
    cudaGetSymbolAddress((void**)&downTh, g_downTh);   cudaGetSymbolAddress((void**)&downTl, g_downTl);
    cudaGetSymbolAddress((void**)&fc1Th, g_fc1Th);     cudaGetSymbolAddress((void**)&fc1Tl, g_fc1Tl);
    cudaGetSymbolAddress((void**)&fc2Th, g_fc2Th);     cudaGetSymbolAddress((void**)&fc2Tl, g_fc2Tl);

    cudaFuncSetAttribute(attn_kernel, cudaFuncAttributeMaxDynamicSharedMemorySize, ATT_SMEM);
    cudaFuncSetAttribute(gemm_mma<EPI_NONE, false>, cudaFuncAttributeMaxDynamicSharedMemorySize, GEMM_SMEM);
    cudaFuncSetAttribute(gemm_mma<EPI_BIAS, false>, cudaFuncAttributeMaxDynamicSharedMemorySize, GEMM_SMEM);
    cudaFuncSetAttribute(gemm_mma<EPI_BIAS_RES, false>, cudaFuncAttributeMaxDynamicSharedMemorySize, GEMM_SMEM);
    cudaFuncSetAttribute(gemm_mma<EPI_BIAS_SILU, false>, cudaFuncAttributeMaxDynamicSharedMemorySize, GEMM_SMEM);
    cudaFuncSetAttribute(gemm_mma<EPI_BIAS_MUL, true>, cudaFuncAttributeMaxDynamicSharedMemorySize, GEMM_SMEM);
    cudaFuncSetAttribute(gemm_mma<EPI_BIAS_GELU, true>, cudaFuncAttributeMaxDynamicSharedMemorySize, GEMM_SMEM);

    // ---- activation split ----
    conv_act<<<(T_TOK * PATCH_KP + 255) / 256, 256>>>(x, xh, xl, T_TOK, PATCH_IN, PATCH_KP);

    // ---- batched weight transpose+split ----
    {
        ConvTable tb;
        int tc = 0, si = 0;
        auto add = [&](const float* s, bf16* dh, bf16* dl, int K, int N, int Kp, int Np) {
            const int tx = (Kp + 31) / 32, ty = (Np + 31) / 32;
            tb.seg[si] = { s, dh, dl, K, N, Kp, tc, tx };
            tc += tx * ty; si++;
        };
        add(patchw, patchTh, patchTl, PATCH_IN, 1280, PATCH_KP, 1280);
        for (int l = 0; l < DEPTH; l++) {
            add(qkvw + (size_t)l * 1280 * 3840, qkvTh + (size_t)l * 3840 * 1280,
                qkvTl + (size_t)l * 3840 * 1280, 1280, 3840, 1280, 3840);
            add(projw + (size_t)l * 1280 * 1280, projTh + (size_t)l * 1280 * 1280,
                projTl + (size_t)l * 1280 * 1280, 1280, 1280, 1280, 1280);
            add(gw + (size_t)l * 1280 * FF_DIM, gateTh + (size_t)l * FF_PAD * 1280,
                gateTl + (size_t)l * FF_PAD * 1280, 1280, FF_DIM, 1280, FF_PAD);
            add(uw + (size_t)l * 1280 * FF_DIM, upTh + (size_t)l * FF_PAD * 1280,
                upTl + (size_t)l * FF_PAD * 1280, 1280, FF_DIM, 1280, FF_PAD);
            add(dw + (size_t)l * FF_DIM * 1280, downTh + (size_t)l * 1280 * FF_PAD,
                downTl + (size_t)l * 1280 * FF_PAD, FF_DIM, 1280, FF_PAD, 1280);
        }
        add(f1w, fc1Th, fc1Tl, 5120, 5120, 5120, 5120);
        add(f2w, fc2Th, fc2Tl, 5120, 3584, 5120, 3584);
        conv_all<<<tc, dim3(32, 8)>>>(tb);
    }

    // ---- patch embed ----
    gemm_mma<EPI_NONE, false><<<dim3(16, 10), 256, GEMM_SMEM>>>(
        xh, xl, patchTh, patchTl, nullptr, nullptr, h, nullptr, nullptr,
        PATCH_KP, 1280, 1280, 0);

    for (int l = 0; l < DEPTH; l++) {
        const size_t lD = (size_t)l * D_MODEL;
        rmsnorm_pair<<<T_TOK, 256>>>(h, n1s + lD, nh, nl);
        gemm_mma<EPI_BIAS, false><<<dim3(16, 30), 256, GEMM_SMEM>>>(
            nh, nl, qkvTh + (size_t)l * 3840 * 1280, qkvTl + (size_t)l * 3840 * 1280,
            qkvb + (size_t)l * 3840, nullptr, qkv, nullptr, nullptr, 1280, 3840, 3840, 0);
        attn_kernel<<<dim3(NWIN, H_HEADS), 256, ATT_SMEM>>>(qkv, rot, ath, atl);
        gemm_mma<EPI_BIAS_RES, false><<<dim3(16, 10), 256, GEMM_SMEM>>>(
            ath, atl, projTh + (size_t)l * 1280 * 1280, projTl + (size_t)l * 1280 * 1280,
            projb + lD, h, h, nullptr, nullptr, 1280, 1280, 1280, 1280);
        rmsnorm_pair<<<T_TOK, 256>>>(h, n2s + lD, nh, nl);
        gemm_mma<EPI_BIAS_SILU, false><<<dim3(16, 27), 256, GEMM_SMEM>>>(
            nh, nl, gateTh + (size_t)l * FF_PAD * 1280, gateTl + (size_t)l * FF_PAD * 1280,
            gb + (size_t)l * FF_DIM, nullptr, gate, nullptr, nullptr, 1280, FF_DIM, FF_DIM, 0);
        gemm_mma<EPI_BIAS_MUL, true><<<dim3(16, 27), 256, GEMM_SMEM>>>(
            nh, nl, upTh + (size_t)l * FF_PAD * 1280, upTl + (size_t)l * FF_PAD * 1280,
            ub + (size_t)l * FF_DIM, gate, nullptr, uph, upl, 1280, FF_DIM, FF_PAD, FF_DIM);
        gemm_mma<EPI_BIAS_RES, false><<<dim3(16, 10), 256, GEMM_SMEM>>>(
            uph, upl, downTh + (size_t)l * 1280 * FF_PAD, downTl + (size_t)l * 1280 * FF_PAD,
            db + lD, h, h, nullptr, nullptr, FF_PAD, 1280, 1280, 1280);
    }

    rmsnorm_pair<<<T_TOK, 256>>>(h, lnq, nh, nl);
    gemm_mma<EPI_BIAS_GELU, true><<<dim3(4, 40), 256, GEMM_SMEM>>>(
        nh, nl, fc1Th, fc1Tl, f1b, nullptr, nullptr, f1h, f1l, 5120, 5120, 5120, 0);
    gemm_mma<EPI_BIAS, false><<<dim3(4, 28), 256, GEMM_SMEM>>>(
        f1h, f1l, fc2Th, fc2Tl, f2b, nullptr, out, nullptr, nullptr, 5120, 3584, 3584, 0);
}